// round 1
// baseline (speedup 1.0000x reference)
#include <cuda_runtime.h>
#include <cuda_bf16.h>

#define Hc 128
#define Wc 128
#define Cc 16
#define Nc 128
#define TW 136   // tile row stride in floats (16B-aligned rows)
#define TR 132   // tile rows = H + 4 halo
#define THREADS 256

// Dynamic shared tile: zero-padded plane. smem col = input col + 4, smem row = input row + 2.
extern __shared__ float tile[];

__global__ void __launch_bounds__(THREADS, 3)
dirsum_kernel(const float* __restrict__ in, float* __restrict__ out) {
    const int plane = blockIdx.x;          // n*C + c
    const int n = plane / Cc;
    const int c = plane % Cc;
    const int tid = threadIdx.x;

    // ---- zero entire tile (covers halos) ----
    const float4 z = make_float4(0.f, 0.f, 0.f, 0.f);
    #pragma unroll 4
    for (int i = tid; i < TR * TW / 4; i += THREADS)
        reinterpret_cast<float4*>(tile)[i] = z;
    __syncthreads();

    // ---- load interior plane (128x128) with float4, coalesced ----
    const float4* src = reinterpret_cast<const float4*>(in + (size_t)plane * Hc * Wc);
    #pragma unroll 4
    for (int i = tid; i < Hc * Wc / 4; i += THREADS) {
        const int row  = i >> 5;       // 32 float4 per input row
        const int col4 = i & 31;
        *reinterpret_cast<float4*>(&tile[(row + 2) * TW + 4 + col4 * 4]) = src[i];
    }
    __syncthreads();

    const size_t hw = (size_t)Hc * Wc;
    float* __restrict__ out0 = out + ((size_t)n * 4 * Cc + c) * hw;  // hor plane base
    float* __restrict__ out1 = out0 + (size_t)Cc * hw;               // ver
    float* __restrict__ out2 = out1 + (size_t)Cc * hw;               // diag
    float* __restrict__ out3 = out2 + (size_t)Cc * hw;               // adiag

    // Each iteration: thread handles 4 consecutive w at one h. One warp = one row.
    #pragma unroll
    for (int it = 0; it < (Hc * Wc / 4) / THREADS; ++it) {
        const int pos4 = tid + it * THREADS;   // float4 index in the plane
        const int h = pos4 >> 5;
        const int w = (pos4 & 31) * 4;

        // 5x12 register patch: a[d][k] = smem[h+d][w+k]  (smem coords)
        float a[5][12];
        #pragma unroll
        for (int d = 0; d < 5; ++d) {
            #pragma unroll
            for (int q = 0; q < 3; ++q) {
                const float4 v = *reinterpret_cast<const float4*>(
                    &tile[(h + d) * TW + w + 4 * q]);
                a[d][4 * q + 0] = v.x;
                a[d][4 * q + 1] = v.y;
                a[d][4 * q + 2] = v.z;
                a[d][4 * q + 3] = v.w;
            }
        }

        // window col j for output (h, w+j): input col w+j-2+d -> smem col w+j+2+d -> array j+2+d
        float hv[4], vv[4], dv[4], av[4];
        #pragma unroll
        for (int j = 0; j < 4; ++j) {
            float sh = 0.f, sv = 0.f, sd = 0.f, sa = 0.f;
            #pragma unroll
            for (int d = 0; d < 5; ++d) {
                sh += a[2][j + d + 2];   // horizontal: fixed row, sliding col
                sv += a[d][j + 4];       // vertical:   sliding row, fixed col
                sd += a[d][j + d + 2];   // main diag
                sa += a[d][j + 6 - d];   // anti diag
            }
            hv[j] = sh; vv[j] = sv; dv[j] = sd; av[j] = sa;
        }

        const size_t o = (size_t)h * Wc + w;
        *reinterpret_cast<float4*>(out0 + o) = make_float4(hv[0], hv[1], hv[2], hv[3]);
        *reinterpret_cast<float4*>(out1 + o) = make_float4(vv[0], vv[1], vv[2], vv[3]);
        *reinterpret_cast<float4*>(out2 + o) = make_float4(dv[0], dv[1], dv[2], dv[3]);
        *reinterpret_cast<float4*>(out3 + o) = make_float4(av[0], av[1], av[2], av[3]);
    }
}

extern "C" void kernel_launch(void* const* d_in, const int* in_sizes, int n_in,
                              void* d_out, int out_size) {
    const float* in = (const float*)d_in[0];
    float* out = (float*)d_out;
    const size_t smem = (size_t)TR * TW * sizeof(float);   // 71808 B
    cudaFuncSetAttribute(dirsum_kernel, cudaFuncAttributeMaxDynamicSharedMemorySize, (int)smem);
    dirsum_kernel<<<Nc * Cc, THREADS, smem>>>(in, out);
}

// round 2
// speedup vs baseline: 1.0597x; 1.0597x over previous
#include <cuda_runtime.h>
#include <cuda_bf16.h>

#define Hc 128
#define Wc 128
#define Cc 16
#define Nc 128
#define TW 136   // tile row stride in floats (16B-aligned rows)
#define TR 132   // tile rows = H + 4 halo
#define THREADS 256
#define SEG 16   // output rows per thread

extern __shared__ float tile[];

__global__ void __launch_bounds__(THREADS, 3)
dirsum_kernel(const float* __restrict__ in, float* __restrict__ out) {
    const int plane = blockIdx.x;          // n*C + c
    const int tid = threadIdx.x;

    // ---- zero entire tile (covers halos) ----
    const float4 z = make_float4(0.f, 0.f, 0.f, 0.f);
    #pragma unroll 4
    for (int i = tid; i < TR * TW / 4; i += THREADS)
        reinterpret_cast<float4*>(tile)[i] = z;
    __syncthreads();

    // ---- load interior plane (128x128) with float4, coalesced ----
    const float4* src = reinterpret_cast<const float4*>(in + (size_t)plane * Hc * Wc);
    #pragma unroll 4
    for (int i = tid; i < Hc * Wc / 4; i += THREADS) {
        const int row  = i >> 5;
        const int col4 = i & 31;
        *reinterpret_cast<float4*>(&tile[(row + 2) * TW + 4 + col4 * 4]) = src[i];
    }
    __syncthreads();

    const int n = plane / Cc;
    const int c = plane % Cc;
    const size_t hw = (size_t)Hc * Wc;
    float* __restrict__ out0 = out + ((size_t)n * 4 * Cc + c) * hw;  // hor
    float* __restrict__ out1 = out0 + (size_t)Cc * hw;               // ver
    float* __restrict__ out2 = out1 + (size_t)Cc * hw;               // diag
    float* __restrict__ out3 = out2 + (size_t)Cc * hw;               // adiag

    // Thread owns columns [w, w+4) over rows [h0, h0+SEG).
    const int lane = tid & 31;
    const int seg  = tid >> 5;
    const int w    = lane * 4;
    const int h0   = seg * SEG;

    // Ring: a[d][m] = input[h-2+d][w-2+m], m = 0..8 (smem col w+m, k = m+2)
    float a[5][9];
    #pragma unroll
    for (int d = 0; d < 4; ++d) {
        const float* r = &tile[(h0 + d) * TW + w];
        const float4 v0 = *reinterpret_cast<const float4*>(r);
        const float4 v1 = *reinterpret_cast<const float4*>(r + 4);
        const float4 v2 = *reinterpret_cast<const float4*>(r + 8);
        a[d][0] = v0.z; a[d][1] = v0.w;
        a[d][2] = v1.x; a[d][3] = v1.y; a[d][4] = v1.z; a[d][5] = v1.w;
        a[d][6] = v2.x; a[d][7] = v2.y; a[d][8] = v2.z;
    }

    const size_t o = (size_t)h0 * Wc + w;

    #pragma unroll
    for (int i = 0; i < SEG; ++i) {
        // load the one new row (input row h0+i+2 -> smem row h0+i+4)
        {
            const float* r = &tile[(h0 + i + 4) * TW + w];
            const float4 v0 = *reinterpret_cast<const float4*>(r);
            const float4 v1 = *reinterpret_cast<const float4*>(r + 4);
            const float4 v2 = *reinterpret_cast<const float4*>(r + 8);
            a[4][0] = v0.z; a[4][1] = v0.w;
            a[4][2] = v1.x; a[4][3] = v1.y; a[4][4] = v1.z; a[4][5] = v1.w;
            a[4][6] = v2.x; a[4][7] = v2.y; a[4][8] = v2.z;
        }

        const size_t oo = o + (size_t)i * Wc;

        // horizontal: center row a[2], m = j..j+4
        {
            const float r0 = a[2][0] + a[2][1] + a[2][2] + a[2][3] + a[2][4];
            const float r1 = a[2][1] + a[2][2] + a[2][3] + a[2][4] + a[2][5];
            const float r2 = a[2][2] + a[2][3] + a[2][4] + a[2][5] + a[2][6];
            const float r3 = a[2][3] + a[2][4] + a[2][5] + a[2][6] + a[2][7];
            *reinterpret_cast<float4*>(out0 + oo) = make_float4(r0, r1, r2, r3);
        }
        // vertical: column m = j+2, rows a[0..4]
        {
            const float r0 = a[0][2] + a[1][2] + a[2][2] + a[3][2] + a[4][2];
            const float r1 = a[0][3] + a[1][3] + a[2][3] + a[3][3] + a[4][3];
            const float r2 = a[0][4] + a[1][4] + a[2][4] + a[3][4] + a[4][4];
            const float r3 = a[0][5] + a[1][5] + a[2][5] + a[3][5] + a[4][5];
            *reinterpret_cast<float4*>(out1 + oo) = make_float4(r0, r1, r2, r3);
        }
        // main diag: a[d][j+d]
        {
            const float r0 = a[0][0] + a[1][1] + a[2][2] + a[3][3] + a[4][4];
            const float r1 = a[0][1] + a[1][2] + a[2][3] + a[3][4] + a[4][5];
            const float r2 = a[0][2] + a[1][3] + a[2][4] + a[3][5] + a[4][6];
            const float r3 = a[0][3] + a[1][4] + a[2][5] + a[3][6] + a[4][7];
            *reinterpret_cast<float4*>(out2 + oo) = make_float4(r0, r1, r2, r3);
        }
        // anti diag: a[d][j+4-d]
        {
            const float r0 = a[0][4] + a[1][3] + a[2][2] + a[3][1] + a[4][0];
            const float r1 = a[0][5] + a[1][4] + a[2][3] + a[3][2] + a[4][1];
            const float r2 = a[0][6] + a[1][5] + a[2][4] + a[3][3] + a[4][2];
            const float r3 = a[0][7] + a[1][6] + a[2][5] + a[3][4] + a[4][3];
            *reinterpret_cast<float4*>(out3 + oo) = make_float4(r0, r1, r2, r3);
        }

        // shift ring (fully unrolled loop -> register renaming, no MOVs)
        #pragma unroll
        for (int d = 0; d < 4; ++d)
            #pragma unroll
            for (int m = 0; m < 9; ++m)
                a[d][m] = a[d + 1][m];
    }
}

extern "C" void kernel_launch(void* const* d_in, const int* in_sizes, int n_in,
                              void* d_out, int out_size) {
    const float* in = (const float*)d_in[0];
    float* out = (float*)d_out;
    const size_t smem = (size_t)TR * TW * sizeof(float);   // 71808 B
    cudaFuncSetAttribute(dirsum_kernel, cudaFuncAttributeMaxDynamicSharedMemorySize, (int)smem);
    dirsum_kernel<<<Nc * Cc, THREADS, smem>>>(in, out);
}

// round 3
// speedup vs baseline: 1.0663x; 1.0062x over previous
#include <cuda_runtime.h>
#include <cuda_bf16.h>

#define Hc 128
#define Wc 128
#define Cc 16
#define Nc 128
#define TW 136          // tile row stride in floats
#define TRH 68          // tile rows: 64 interior + 4 halo
#define THREADS 256
#define SEG 8           // output rows per thread

extern __shared__ float tile[];

__global__ void __launch_bounds__(THREADS, 4)
dirsum_kernel(const float* __restrict__ in, float* __restrict__ out) {
    const int b     = blockIdx.x;
    const int plane = b >> 1;          // n*C + c
    const int hbase = (b & 1) << 6;    // 0 or 64
    const int tid   = threadIdx.x;

    // ---- fused predicated fill: interior <- global, halo <- 0 ----
    const float4* src = reinterpret_cast<const float4*>(in + (size_t)plane * Hc * Wc);
    float4* t4 = reinterpret_cast<float4*>(tile);
    #pragma unroll 5
    for (int i = tid; i < TRH * TW / 4; i += THREADS) {
        const int t = i / (TW / 4);            // tile row
        const int q = i - t * (TW / 4);        // float4 within row
        const int g = hbase + t - 2;           // global input row
        float4 v = make_float4(0.f, 0.f, 0.f, 0.f);
        if ((unsigned)g < (unsigned)Hc && q >= 1 && q <= 32)
            v = src[g * (Wc / 4) + (q - 1)];
        t4[i] = v;
    }
    __syncthreads();

    const int n = plane / Cc;
    const int c = plane % Cc;
    const size_t hw = (size_t)Hc * Wc;
    float* __restrict__ ob = out + ((size_t)n * 4 * Cc + c) * hw;
    const int dstep = Cc * Hc * Wc;            // stride between direction groups

    // Thread owns columns [w, w+4) over local rows [h0, h0+SEG).
    const int lane = tid & 31;
    const int seg  = tid >> 5;
    const int w    = lane * 4;
    const int h0   = seg * SEG;                // local (tile row h0 = output row hbase+h0 - window top)

    // Ring: a[d][m] = input[r-2+d][w-2+m], m=0..8
    float a[5][9];
    #pragma unroll
    for (int d = 0; d < 4; ++d) {
        const float* r = &tile[(h0 + d) * TW + w];
        const float4 v0 = *reinterpret_cast<const float4*>(r);
        const float4 v1 = *reinterpret_cast<const float4*>(r + 4);
        const float4 v2 = *reinterpret_cast<const float4*>(r + 8);
        a[d][0] = v0.z; a[d][1] = v0.w;
        a[d][2] = v1.x; a[d][3] = v1.y; a[d][4] = v1.z; a[d][5] = v1.w;
        a[d][6] = v2.x; a[d][7] = v2.y; a[d][8] = v2.z;
    }

    int oo = (hbase + h0) * Wc + w;

    #pragma unroll
    for (int i = 0; i < SEG; ++i) {
        // load the one new ring row (tile row h0+i+4)
        {
            const float* r = &tile[(h0 + i + 4) * TW + w];
            const float4 v0 = *reinterpret_cast<const float4*>(r);
            const float4 v1 = *reinterpret_cast<const float4*>(r + 4);
            const float4 v2 = *reinterpret_cast<const float4*>(r + 8);
            a[4][0] = v0.z; a[4][1] = v0.w;
            a[4][2] = v1.x; a[4][3] = v1.y; a[4][4] = v1.z; a[4][5] = v1.w;
            a[4][6] = v2.x; a[4][7] = v2.y; a[4][8] = v2.z;
        }

        // horizontal
        {
            const float r0 = a[2][0] + a[2][1] + a[2][2] + a[2][3] + a[2][4];
            const float r1 = a[2][1] + a[2][2] + a[2][3] + a[2][4] + a[2][5];
            const float r2 = a[2][2] + a[2][3] + a[2][4] + a[2][5] + a[2][6];
            const float r3 = a[2][3] + a[2][4] + a[2][5] + a[2][6] + a[2][7];
            *reinterpret_cast<float4*>(ob + oo) = make_float4(r0, r1, r2, r3);
        }
        // vertical
        {
            const float r0 = a[0][2] + a[1][2] + a[2][2] + a[3][2] + a[4][2];
            const float r1 = a[0][3] + a[1][3] + a[2][3] + a[3][3] + a[4][3];
            const float r2 = a[0][4] + a[1][4] + a[2][4] + a[3][4] + a[4][4];
            const float r3 = a[0][5] + a[1][5] + a[2][5] + a[3][5] + a[4][5];
            *reinterpret_cast<float4*>(ob + dstep + oo) = make_float4(r0, r1, r2, r3);
        }
        // main diag
        {
            const float r0 = a[0][0] + a[1][1] + a[2][2] + a[3][3] + a[4][4];
            const float r1 = a[0][1] + a[1][2] + a[2][3] + a[3][4] + a[4][5];
            const float r2 = a[0][2] + a[1][3] + a[2][4] + a[3][5] + a[4][6];
            const float r3 = a[0][3] + a[1][4] + a[2][5] + a[3][6] + a[4][7];
            *reinterpret_cast<float4*>(ob + 2 * dstep + oo) = make_float4(r0, r1, r2, r3);
        }
        // anti diag
        {
            const float r0 = a[0][4] + a[1][3] + a[2][2] + a[3][1] + a[4][0];
            const float r1 = a[0][5] + a[1][4] + a[2][3] + a[3][2] + a[4][1];
            const float r2 = a[0][6] + a[1][5] + a[2][4] + a[3][3] + a[4][2];
            const float r3 = a[0][7] + a[1][6] + a[2][5] + a[3][4] + a[4][3];
            *reinterpret_cast<float4*>(ob + 3 * dstep + oo) = make_float4(r0, r1, r2, r3);
        }

        oo += Wc;

        // shift ring (unrolled -> register renaming)
        #pragma unroll
        for (int d = 0; d < 4; ++d)
            #pragma unroll
            for (int m = 0; m < 9; ++m)
                a[d][m] = a[d + 1][m];
    }
}

extern "C" void kernel_launch(void* const* d_in, const int* in_sizes, int n_in,
                              void* d_out, int out_size) {
    const float* in = (const float*)d_in[0];
    float* out = (float*)d_out;
    const size_t smem = (size_t)TRH * TW * sizeof(float);   // 36992 B
    cudaFuncSetAttribute(dirsum_kernel, cudaFuncAttributeMaxDynamicSharedMemorySize, (int)smem);
    dirsum_kernel<<<Nc * Cc * 2, THREADS, smem>>>(in, out);
}